// round 3
// baseline (speedup 1.0000x reference)
#include <cuda_runtime.h>
#include <math.h>

#define BB      2
#define NQ      5376
#define NVAL    5376
#define CDIM    256
#define HEADS   8
#define HD      32
#define LEVELS  3
#define POINTS  4
#define M_TOT   (BB * NQ)        // 10752

// Scratch (device globals: no allocation allowed in kernel_launch)
__device__ float g_v[BB * NVAL * CDIM];       // projected value
__device__ float g_off[BB * NQ * 192];        // sampling offsets
__device__ float g_a[BB * NQ * 96];           // attention logits
__device__ float g_attn[BB * NQ * CDIM];      // sampled output (pre-Wo)

__constant__ int c_H[LEVELS]     = {64, 32, 16};
__constant__ int c_W[LEVELS]     = {64, 32, 16};
__constant__ int c_start[LEVELS] = {0, 4096, 5120};

// ---------------------------------------------------------------------------
// C = A @ W^T + bias.  A: [M,K] row-major, W: [N,K] row-major, C: [M,N].
// Tiles: BM=BN=64, BK=16. 256 threads, 4x4 per thread.
// M % 64 == 0 and K % 16 == 0 are guaranteed here; N may be ragged (96).
// ---------------------------------------------------------------------------
__global__ __launch_bounds__(256) void sgemm_wt(
    const float* __restrict__ A, const float* __restrict__ W,
    const float* __restrict__ bias, float* __restrict__ C,
    int M, int N, int K)
{
    __shared__ float As[16][68];   // pad 68: 16B-aligned rows, mild conflicts only
    __shared__ float Bs[16][68];

    const int tid = threadIdx.x;
    const int tx  = tid & 15;        // 0..15 -> col group
    const int ty  = tid >> 4;        // 0..15 -> row group
    const int row0 = blockIdx.y * 64;
    const int col0 = blockIdx.x * 64;

    // loader mapping: each thread loads one float4 (64 rows x 16 k / 4)
    const int lm = tid >> 2;          // 0..63 row/col within tile
    const int lk = (tid & 3) * 4;     // 0,4,8,12

    float acc[4][4] = {};

    for (int kt = 0; kt < K; kt += 16) {
        // A tile
        {
            float4 va = *reinterpret_cast<const float4*>(
                &A[(size_t)(row0 + lm) * K + kt + lk]);
            As[lk + 0][lm] = va.x; As[lk + 1][lm] = va.y;
            As[lk + 2][lm] = va.z; As[lk + 3][lm] = va.w;
        }
        // W tile (B^T), zero-fill past N
        {
            float4 vb = make_float4(0.f, 0.f, 0.f, 0.f);
            if (col0 + lm < N)
                vb = *reinterpret_cast<const float4*>(
                    &W[(size_t)(col0 + lm) * K + kt + lk]);
            Bs[lk + 0][lm] = vb.x; Bs[lk + 1][lm] = vb.y;
            Bs[lk + 2][lm] = vb.z; Bs[lk + 3][lm] = vb.w;
        }
        __syncthreads();

        #pragma unroll
        for (int k = 0; k < 16; k++) {
            float4 a4 = *reinterpret_cast<const float4*>(&As[k][ty * 4]);
            float4 b4 = *reinterpret_cast<const float4*>(&Bs[k][tx * 4]);
            float ar[4] = {a4.x, a4.y, a4.z, a4.w};
            float br[4] = {b4.x, b4.y, b4.z, b4.w};
            #pragma unroll
            for (int i = 0; i < 4; i++)
                #pragma unroll
                for (int j = 0; j < 4; j++)
                    acc[i][j] = fmaf(ar[i], br[j], acc[i][j]);
        }
        __syncthreads();
    }

    #pragma unroll
    for (int i = 0; i < 4; i++) {
        int r = row0 + ty * 4 + i;
        #pragma unroll
        for (int j = 0; j < 4; j++) {
            int c = col0 + tx * 4 + j;
            if (c < N)
                C[(size_t)r * N + c] = acc[i][j] + bias[c];
        }
    }
}

// ---------------------------------------------------------------------------
// Sampling: one warp per (b, q, h). lane = channel d (HD=32).
// Reads g_v, g_off, g_a; writes g_attn[b,q, h*HD + d].
// ---------------------------------------------------------------------------
__global__ __launch_bounds__(256) void msda_sample(const float* __restrict__ rp)
{
    const int w = blockIdx.x * (blockDim.x >> 5) + (threadIdx.x >> 5);
    const int lane = threadIdx.x & 31;
    if (w >= BB * NQ * HEADS) return;

    const int h  = w % HEADS;
    const int bq = w / HEADS;          // b*NQ + q
    const int b  = bq / NQ;

    // softmax over 12 (LEVELS*POINTS) logits for this (b,q,h)
    float av = -INFINITY;
    if (lane < LEVELS * POINTS)
        av = g_a[bq * 96 + h * 12 + lane];
    float mx = av;
    #pragma unroll
    for (int s = 16; s; s >>= 1) mx = fmaxf(mx, __shfl_xor_sync(0xffffffffu, mx, s));
    float e = (lane < LEVELS * POINTS) ? __expf(av - mx) : 0.f;
    float se = e;
    #pragma unroll
    for (int s = 16; s; s >>= 1) se += __shfl_xor_sync(0xffffffffu, se, s);
    const float wsm = e / se;

    const float rx = rp[bq * 2 + 0];
    const float ry = rp[bq * 2 + 1];
    const float* offp = &g_off[(size_t)bq * 192 + h * (LEVELS * POINTS * 2)];

    float acc = 0.f;
    #pragma unroll
    for (int l = 0; l < LEVELS; l++) {
        const int H = c_H[l], W = c_W[l], st = c_start[l];
        const float* vl = &g_v[((size_t)b * NVAL + st) * CDIM + h * HD + lane];
        const float fW = (float)W, fH = (float)H;
        #pragma unroll
        for (int p = 0; p < POINTS; p++) {
            const float aw = __shfl_sync(0xffffffffu, wsm, l * POINTS + p);
            float lx = fminf(fmaxf(rx + offp[(l * POINTS + p) * 2 + 0], 0.f), 1.f);
            float ly = fminf(fmaxf(ry + offp[(l * POINTS + p) * 2 + 1], 0.f), 1.f);
            float x = lx * fW - 0.5f;
            float y = ly * fH - 0.5f;
            float x0f = floorf(x), y0f = floorf(y);
            float wx1 = x - x0f,  wy1 = y - y0f;
            int x0 = (int)x0f, y0 = (int)y0f;
            #pragma unroll
            for (int dy = 0; dy < 2; dy++) {
                #pragma unroll
                for (int dx = 0; dx < 2; dx++) {
                    int ix = x0 + dx, iy = y0 + dy;
                    if (ix >= 0 && ix < W && iy >= 0 && iy < H) {
                        float wt = (dx ? wx1 : 1.f - wx1) * (dy ? wy1 : 1.f - wy1);
                        acc = fmaf(vl[(iy * W + ix) * CDIM], wt * aw, acc);
                    }
                }
            }
        }
    }
    g_attn[(size_t)bq * CDIM + h * HD + lane] = acc;
}

// ---------------------------------------------------------------------------
extern "C" void kernel_launch(void* const* d_in, const int* in_sizes, int n_in,
                              void* d_out, int out_size)
{
    const float* query = (const float*)d_in[0];   // [B,NQ,C]
    const float* refp  = (const float*)d_in[1];   // [B,NQ,2]
    const float* value = (const float*)d_in[2];   // [B,NV,C]
    const float* Wv    = (const float*)d_in[3];   // [C,C]
    const float* bv    = (const float*)d_in[4];   // [C]
    const float* Woff  = (const float*)d_in[5];   // [192,C]
    const float* boff  = (const float*)d_in[6];   // [192]
    const float* Wa    = (const float*)d_in[7];   // [96,C]
    const float* ba    = (const float*)d_in[8];   // [96]
    const float* Wo    = (const float*)d_in[9];   // [C,C]
    const float* bo    = (const float*)d_in[10];  // [C]
    float* out = (float*)d_out;

    float* pv;   cudaGetSymbolAddress((void**)&pv,   g_v);
    float* poff; cudaGetSymbolAddress((void**)&poff, g_off);
    float* pa;   cudaGetSymbolAddress((void**)&pa,   g_a);
    float* patt; cudaGetSymbolAddress((void**)&patt, g_attn);

    dim3 blk(256);

    // 1. v = value @ Wv^T + bv
    sgemm_wt<<<dim3(CDIM / 64, M_TOT / 64), blk>>>(value, Wv, bv, pv, M_TOT, CDIM, CDIM);
    // 2. off = query @ Woff^T + boff
    sgemm_wt<<<dim3(192 / 64, M_TOT / 64), blk>>>(query, Woff, boff, poff, M_TOT, 192, CDIM);
    // 3. a = query @ Wa^T + ba
    sgemm_wt<<<dim3((96 + 63) / 64, M_TOT / 64), blk>>>(query, Wa, ba, pa, M_TOT, 96, CDIM);
    // 4. sampling (one warp per (b,q,h))
    {
        int warps = BB * NQ * HEADS;                 // 86016
        int blocks = (warps + 7) / 8;                // 8 warps / block
        msda_sample<<<blocks, blk>>>(refp);
    }
    // 5. out = attn @ Wo^T + bo
    sgemm_wt<<<dim3(CDIM / 64, M_TOT / 64), blk>>>(patt, Wo, bo, out, M_TOT, CDIM, CDIM);
}

// round 6
// speedup vs baseline: 1.3977x; 1.3977x over previous
#include <cuda_runtime.h>
#include <math.h>

#define BB      2
#define NQ      5376
#define NVAL    5376
#define CDIM    256
#define HEADS   8
#define HD      32
#define LEVELS  3
#define POINTS  4
#define M_TOT   (BB * NQ)        // 10752

// Scratch (device globals: no allocation allowed in kernel_launch)
__device__ float g_v[BB * NVAL * CDIM];       // projected value
__device__ float g_off[BB * NQ * 192];        // sampling offsets
__device__ float g_a[BB * NQ * 96];           // attention logits
__device__ float g_attn[BB * NQ * CDIM];      // sampled output (pre-Wo)

// ---------------------------------------------------------------------------
// C = A @ W^T + bias.  A: [M,K] row-major, W: [N,K] row-major, C: [M,N].
// BM=BN=128, BK=8, 256 threads, 8x8 per thread. M%128==0, K%8==0 guaranteed;
// N may be ragged (96/192) -> zero-fill W tile + guarded stores.
// ---------------------------------------------------------------------------
__global__ __launch_bounds__(256, 2) void sgemm128(
    const float* __restrict__ A, const float* __restrict__ W,
    const float* __restrict__ bias, float* __restrict__ C,
    int M, int N, int K)
{
    __shared__ float As[8][132];   // +4 pad: conflict-free transposed stores
    __shared__ float Bs[8][132];

    const int tid  = threadIdx.x;
    const int tx   = tid & 15;         // col group 0..15
    const int ty   = tid >> 4;         // row group 0..15
    const int row0 = blockIdx.y * 128;
    const int col0 = blockIdx.x * 128;

    // loader: each thread loads one float4 (128 rows x 8 k / 4)
    const int lr = tid >> 1;           // 0..127
    const int lk = (tid & 1) * 4;      // 0 or 4

    const float* Aptr = A + (size_t)(row0 + lr) * K + lk;
    const float* Wptr = W + (size_t)(col0 + lr) * K + lk;
    const bool wvalid = (col0 + lr) < N;

    float acc[8][8] = {};

    for (int kt = 0; kt < K; kt += 8) {
        float4 va = *reinterpret_cast<const float4*>(Aptr + kt);
        float4 vb = make_float4(0.f, 0.f, 0.f, 0.f);
        if (wvalid)
            vb = *reinterpret_cast<const float4*>(Wptr + kt);

        As[lk + 0][lr] = va.x; As[lk + 1][lr] = va.y;
        As[lk + 2][lr] = va.z; As[lk + 3][lr] = va.w;
        Bs[lk + 0][lr] = vb.x; Bs[lk + 1][lr] = vb.y;
        Bs[lk + 2][lr] = vb.z; Bs[lk + 3][lr] = vb.w;
        __syncthreads();

        #pragma unroll
        for (int k = 0; k < 8; k++) {
            float a[8], b[8];
            *reinterpret_cast<float4*>(a)     = *reinterpret_cast<const float4*>(&As[k][ty * 8]);
            *reinterpret_cast<float4*>(a + 4) = *reinterpret_cast<const float4*>(&As[k][ty * 8 + 4]);
            *reinterpret_cast<float4*>(b)     = *reinterpret_cast<const float4*>(&Bs[k][tx * 8]);
            *reinterpret_cast<float4*>(b + 4) = *reinterpret_cast<const float4*>(&Bs[k][tx * 8 + 4]);
            #pragma unroll
            for (int i = 0; i < 8; i++)
                #pragma unroll
                for (int j = 0; j < 8; j++)
                    acc[i][j] = fmaf(a[i], b[j], acc[i][j]);
        }
        __syncthreads();
    }

    #pragma unroll
    for (int i = 0; i < 8; i++) {
        const size_t r = (size_t)(row0 + ty * 8 + i);
        #pragma unroll
        for (int j = 0; j < 8; j++) {
            const int c = col0 + tx * 8 + j;
            if (c < N)
                C[r * N + c] = acc[i][j] + bias[c];
        }
    }
}

// ---------------------------------------------------------------------------
// Sampling: one warp per (b, q, h). lane = channel d (HD=32).
// Lanes 0..11 compute the scalar package for their point in parallel;
// the gather loop broadcasts via shuffles. The 4 bilinear taps share a base
// index: offsets are +CDIM (x) and +W*CDIM (y).
// ---------------------------------------------------------------------------
__global__ __launch_bounds__(256) void msda_sample(const float* __restrict__ rp)
{
    const int w    = blockIdx.x * (blockDim.x >> 5) + (threadIdx.x >> 5);
    const int lane = threadIdx.x & 31;
    if (w >= BB * NQ * HEADS) return;

    const int h  = w & (HEADS - 1);
    const int bq = w >> 3;             // b*NQ + q
    const int b  = bq / NQ;

    // ---- softmax over 12 logits: lane j holds logit j ----
    const int  j   = lane;
    const bool act = (j < LEVELS * POINTS);
    float logit = act ? __ldg(&g_a[bq * 96 + h * 12 + j]) : -INFINITY;
    float mx = logit;
    #pragma unroll
    for (int s = 16; s; s >>= 1) mx = fmaxf(mx, __shfl_xor_sync(0xffffffffu, mx, s));
    float e = act ? __expf(logit - mx) : 0.f;
    float se = e;
    #pragma unroll
    for (int s = 16; s; s >>= 1) se += __shfl_xor_sync(0xffffffffu, se, s);
    const float aw = e / se;           // softmax weight for point j (lanes 0..11)

    // ---- phase A: lanes 0..11 build the scalar package for point j ----
    const float rx = __ldg(&rp[bq * 2 + 0]);
    const float ry = __ldg(&rp[bq * 2 + 1]);

    int   I00 = 0, DXC = 0, DYC = 0;
    float w00 = 0.f, w01 = 0.f, w10 = 0.f, w11 = 0.f;
    {
        const int l  = j >> 2;                       // level (garbage ok for j>=12)
        const int Wl = 64 >> l;
        const int Hl = 64 >> l;
        const int st = (l == 0) ? 0 : ((l == 1) ? 4096 : 5120);

        float2 off = __ldg(reinterpret_cast<const float2*>(
            g_off + (size_t)bq * 192 + h * 24) + (act ? j : 0));

        float lx = fminf(fmaxf(rx + off.x, 0.f), 1.f);
        float ly = fminf(fmaxf(ry + off.y, 0.f), 1.f);
        float x = lx * (float)Wl - 0.5f;
        float y = ly * (float)Hl - 0.5f;
        float x0f = floorf(x), y0f = floorf(y);
        float wx = x - x0f,   wy = y - y0f;
        int x0 = (int)x0f, y0 = (int)y0f;

        // clamped coords + validity (x0 <= Wl-1 and x0+1 >= 0 always hold)
        int cx0 = max(x0, 0);
        int cy0 = max(y0, 0);
        int cx1 = min(x0 + 1, Wl - 1);
        int cy1 = min(y0 + 1, Hl - 1);
        float vx0 = (x0 >= 0)      ? 1.f : 0.f;
        float vx1 = (x0 + 1 < Wl)  ? 1.f : 0.f;
        float vy0 = (y0 >= 0)      ? 1.f : 0.f;
        float vy1 = (y0 + 1 < Hl)  ? 1.f : 0.f;

        float ax0 = (1.f - wx) * vx0, ax1 = wx * vx1;
        float ay0 = (1.f - wy) * vy0 * aw, ay1 = wy * vy1 * aw;
        w00 = ax0 * ay0; w01 = ax1 * ay0;
        w10 = ax0 * ay1; w11 = ax1 * ay1;

        I00 = (st + cy0 * Wl + cx0) * CDIM;
        DXC = (cx1 - cx0) * CDIM;          // 0 or CDIM
        DYC = (cy1 - cy0) * Wl * CDIM;     // 0 or Wl*CDIM
    }

    // ---- phase B: gather, lane = channel ----
    const float* vb = g_v + ((size_t)b * NVAL) * CDIM + h * HD + lane;
    float acc = 0.f;
    #pragma unroll
    for (int p = 0; p < LEVELS * POINTS; p++) {
        const int   I  = __shfl_sync(0xffffffffu, I00, p);
        const int   dx = __shfl_sync(0xffffffffu, DXC, p);
        const int   dy = __shfl_sync(0xffffffffu, DYC, p);
        const float a00 = __shfl_sync(0xffffffffu, w00, p);
        const float a01 = __shfl_sync(0xffffffffu, w01, p);
        const float a10 = __shfl_sync(0xffffffffu, w10, p);
        const float a11 = __shfl_sync(0xffffffffu, w11, p);
        const float* pt = vb + I;
        acc = fmaf(__ldg(pt),           a00, acc);
        acc = fmaf(__ldg(pt + dx),      a01, acc);
        acc = fmaf(__ldg(pt + dy),      a10, acc);
        acc = fmaf(__ldg(pt + dx + dy), a11, acc);
    }
    g_attn[(size_t)bq * CDIM + h * HD + lane] = acc;
}

// ---------------------------------------------------------------------------
extern "C" void kernel_launch(void* const* d_in, const int* in_sizes, int n_in,
                              void* d_out, int out_size)
{
    const float* query = (const float*)d_in[0];   // [B,NQ,C]
    const float* refp  = (const float*)d_in[1];   // [B,NQ,2]
    const float* value = (const float*)d_in[2];   // [B,NV,C]
    const float* Wv    = (const float*)d_in[3];   // [C,C]
    const float* bv    = (const float*)d_in[4];   // [C]
    const float* Woff  = (const float*)d_in[5];   // [192,C]
    const float* boff  = (const float*)d_in[6];   // [192]
    const float* Wa    = (const float*)d_in[7];   // [96,C]
    const float* ba    = (const float*)d_in[8];   // [96]
    const float* Wo    = (const float*)d_in[9];   // [C,C]
    const float* bo    = (const float*)d_in[10];  // [C]
    float* out = (float*)d_out;

    float* pv;   cudaGetSymbolAddress((void**)&pv,   g_v);
    float* poff; cudaGetSymbolAddress((void**)&poff, g_off);
    float* pa;   cudaGetSymbolAddress((void**)&pa,   g_a);
    float* patt; cudaGetSymbolAddress((void**)&patt, g_attn);

    dim3 blk(256);
    const int mb = M_TOT / 128;   // 84

    // 1. v = value @ Wv^T + bv
    sgemm128<<<dim3(2, mb), blk>>>(value, Wv, bv, pv, M_TOT, CDIM, CDIM);
    // 2. off = query @ Woff^T + boff
    sgemm128<<<dim3(2, mb), blk>>>(query, Woff, boff, poff, M_TOT, 192, CDIM);
    // 3. a = query @ Wa^T + ba
    sgemm128<<<dim3(1, mb), blk>>>(query, Wa, ba, pa, M_TOT, 96, CDIM);
    // 4. sampling (one warp per (b,q,h))
    {
        int warps  = BB * NQ * HEADS;              // 86016
        int blocks = (warps + 7) / 8;              // 8 warps / block
        msda_sample<<<blocks, blk>>>(refp);
    }
    // 5. out = attn @ Wo^T + bo
    sgemm128<<<dim3(2, mb), blk>>>(patt, Wo, bo, out, M_TOT, CDIM, CDIM);
}

// round 9
// speedup vs baseline: 3.1180x; 2.2308x over previous
#include <cuda_runtime.h>
#include <cuda_bf16.h>
#include <math.h>
#include <stdint.h>

#define BB      2
#define NQ      5376
#define NVAL    5376
#define CDIM    256
#define HEADS   8
#define HD      32
#define LEVELS  3
#define POINTS  4
#define M_TOT   (BB * NQ)        // 10752
#define KDIM    256

// Scratch (device globals: no allocation allowed in kernel_launch)
__device__ float g_v[BB * NVAL * CDIM];       // projected value
__device__ float g_off[BB * NQ * 192];        // sampling offsets
__device__ float g_a[BB * NQ * 96];           // attention logits
__device__ float g_attn[BB * NQ * CDIM];      // sampled output (pre-Wo)

// ---------------------------------------------------------------------------
__device__ __forceinline__ uint32_t smem_u32(const void* p) {
    uint32_t a;
    asm("{ .reg .u64 t; cvta.to.shared.u64 t, %1; cvt.u32.u64 %0, t; }"
        : "=r"(a) : "l"(p));
    return a;
}

#define LDSM_X4(r0, r1, r2, r3, addr) \
    asm volatile("ldmatrix.sync.aligned.m8n8.x4.shared.b16 {%0,%1,%2,%3}, [%4];" \
        : "=r"(r0), "=r"(r1), "=r"(r2), "=r"(r3) : "r"(addr))

#define MMA_BF16(d, a, b) \
    asm volatile("mma.sync.aligned.m16n8k16.row.col.f32.bf16.bf16.f32 " \
        "{%0,%1,%2,%3}, {%4,%5,%6,%7}, {%8,%9}, {%0,%1,%2,%3};" \
        : "+f"((d)[0]), "+f"((d)[1]), "+f"((d)[2]), "+f"((d)[3]) \
        : "r"((a)[0]), "r"((a)[1]), "r"((a)[2]), "r"((a)[3]), \
          "r"((b)[0]), "r"((b)[1]))

// split fp32 pair -> packed bf16x2 hi and lo
__device__ __forceinline__ void split2(float x, float y, uint32_t& hi, uint32_t& lo) {
    __nv_bfloat16 hx = __float2bfloat16(x);
    __nv_bfloat16 hy = __float2bfloat16(y);
    __nv_bfloat16 lx = __float2bfloat16(x - __bfloat162float(hx));
    __nv_bfloat16 ly = __float2bfloat16(y - __bfloat162float(hy));
    __nv_bfloat162 h; h.x = hx; h.y = hy;
    __nv_bfloat162 l; l.x = lx; l.y = ly;
    hi = *reinterpret_cast<uint32_t*>(&h);
    lo = *reinterpret_cast<uint32_t*>(&l);
}

// swizzled byte offset within a [rows][32] bf16 tile (64B rows, 16B chunks)
__device__ __forceinline__ uint32_t soff(int row, int fq) {
    return (uint32_t)(row * 64 + (((fq >> 1) ^ ((row >> 1) & 3)) << 4) + ((fq & 1) << 3));
}

// ---------------------------------------------------------------------------
// C = A @ W^T + bias via 3xBF16 split mma.sync.
// A: [M,256] f32, W: [N,256] f32, C: [M,N].  BM=128, BN=128, BK=32.
// 8 warps: warp grid 2(m) x 4(n), warp tile 64x32 (4 m-frags x 4 n-frags).
// smem tiles (bf16, swizzled): Ahi[128][32] Alo Bhi[128][32] Blo = 32KB.
// ---------------------------------------------------------------------------
__global__ __launch_bounds__(256, 2) void bf16_gemm(
    const float* __restrict__ A, const float* __restrict__ W,
    const float* __restrict__ bias, float* __restrict__ C, int N)
{
    __shared__ __align__(128) char sm[32768];   // Ahi 0, Alo 8192, Bhi 16384, Blo 24576
    const uint32_t sb = smem_u32(sm);

    const int tid  = threadIdx.x;
    const int lane = tid & 31;
    const int wid  = tid >> 5;
    const int wm   = wid & 1;          // 0..1  (64 rows each)
    const int wn   = wid >> 1;         // 0..3  (32 cols each)
    const int row0 = blockIdx.y * 128;
    const int col0 = blockIdx.x * 128;

    // loader mapping: idx = tid + 256*i -> row = idx>>3 (0..127), fq = idx&7
    const int r8 = tid >> 3;           // base row (step 32 per i)
    const int fq = tid & 7;            // float4 index within 32-float row

    const float* Abase = A + (size_t)(row0 + r8) * KDIM + fq * 4;
    const float* Wbase = W + (size_t)(col0 + r8) * KDIM + fq * 4;
    const int nrem = N - col0;         // valid W rows in this column block

    // precomputed ldmatrix addresses (k-step 0); step 1 = addr ^ 32
    uint32_t aAddr[4], bAddr[2];
    {
        const int mlo = ((lane >> 3) & 1) * 8 + (lane & 7);
        const int ach = lane >> 4;                 // chunk bit for A
        #pragma unroll
        for (int i = 0; i < 4; i++) {
            const int m = wm * 64 + i * 16 + mlo;
            aAddr[i] = sb + m * 64 + ((ach ^ ((m >> 1) & 3)) << 4);
        }
        const int nlo = ((lane >> 4) & 1) * 8 + (lane & 7);
        const int bch = (lane >> 3) & 1;           // chunk bit for B
        #pragma unroll
        for (int p = 0; p < 2; p++) {
            const int n = wn * 32 + p * 16 + nlo;
            bAddr[p] = sb + 16384 + n * 64 + ((bch ^ ((n >> 1) & 3)) << 4);
        }
    }

    float acc[4][4][4] = {};

    for (int c = 0; c < KDIM / 32; c++) {
        const int kt = c * 32;

        // ---- load fp32 chunk, split to bf16 hi/lo, store swizzled ----
        #pragma unroll
        for (int i = 0; i < 4; i++) {
            const int row = r8 + 32 * i;
            const uint32_t off = soff(row, fq);
            {
                float4 v = *reinterpret_cast<const float4*>(Abase + (size_t)(32 * i) * KDIM + kt);
                uint2 h, l;
                split2(v.x, v.y, h.x, l.x);
                split2(v.z, v.w, h.y, l.y);
                *reinterpret_cast<uint2*>(sm + off)        = h;
                *reinterpret_cast<uint2*>(sm + 8192 + off) = l;
            }
            {
                float4 v = make_float4(0.f, 0.f, 0.f, 0.f);
                if (row < nrem)
                    v = *reinterpret_cast<const float4*>(Wbase + (size_t)(32 * i) * KDIM + kt);
                uint2 h, l;
                split2(v.x, v.y, h.x, l.x);
                split2(v.z, v.w, h.y, l.y);
                *reinterpret_cast<uint2*>(sm + 16384 + off) = h;
                *reinterpret_cast<uint2*>(sm + 24576 + off) = l;
            }
        }
        __syncthreads();

        // ---- compute: 2 k16 steps, 48 HMMA each ----
        #pragma unroll
        for (int s = 0; s < 2; s++) {
            const uint32_t sx = s << 5;      // flips chunk-pair bit
            uint32_t ah[4][4], al[4][4];
            #pragma unroll
            for (int i = 0; i < 4; i++) {
                const uint32_t ad = aAddr[i] ^ sx;
                LDSM_X4(ah[i][0], ah[i][1], ah[i][2], ah[i][3], ad);
                LDSM_X4(al[i][0], al[i][1], al[i][2], al[i][3], ad + 8192);
            }
            #pragma unroll
            for (int p = 0; p < 2; p++) {
                uint32_t bh[4], bl[4];
                const uint32_t bd = bAddr[p] ^ sx;
                LDSM_X4(bh[0], bh[1], bh[2], bh[3], bd);
                LDSM_X4(bl[0], bl[1], bl[2], bl[3], bd + 8192);
                #pragma unroll
                for (int i = 0; i < 4; i++) {
                    #pragma unroll
                    for (int jj = 0; jj < 2; jj++) {
                        float* d = acc[i][p * 2 + jj];
                        MMA_BF16(d, ah[i], &bh[jj * 2]);
                        MMA_BF16(d, ah[i], &bl[jj * 2]);
                        MMA_BF16(d, al[i], &bh[jj * 2]);
                    }
                }
            }
        }
        __syncthreads();
    }

    // ---- epilogue: D frag -> C with bias ----
    #pragma unroll
    for (int i = 0; i < 4; i++) {
        const int r = row0 + wm * 64 + i * 16 + (lane >> 2);
        #pragma unroll
        for (int j = 0; j < 4; j++) {
            const int cc = col0 + wn * 32 + j * 8 + (lane & 3) * 2;
            if (cc < N) {
                const float b0 = __ldg(&bias[cc]);
                const float b1 = __ldg(&bias[cc + 1]);
                float2 o0 = make_float2(acc[i][j][0] + b0, acc[i][j][1] + b1);
                float2 o1 = make_float2(acc[i][j][2] + b0, acc[i][j][3] + b1);
                *reinterpret_cast<float2*>(&C[(size_t)r * N + cc])       = o0;
                *reinterpret_cast<float2*>(&C[(size_t)(r + 8) * N + cc]) = o1;
            }
        }
    }
}

// ---------------------------------------------------------------------------
// Sampling: one warp per (b, q, h). lane = channel d (HD=32).
// ---------------------------------------------------------------------------
__global__ __launch_bounds__(256) void msda_sample(const float* __restrict__ rp)
{
    const int w    = blockIdx.x * (blockDim.x >> 5) + (threadIdx.x >> 5);
    const int lane = threadIdx.x & 31;
    if (w >= BB * NQ * HEADS) return;

    const int h  = w & (HEADS - 1);
    const int bq = w >> 3;             // b*NQ + q
    const int b  = bq / NQ;

    // ---- softmax over 12 logits: lane j holds logit j ----
    const int  j   = lane;
    const bool act = (j < LEVELS * POINTS);
    float logit = act ? __ldg(&g_a[bq * 96 + h * 12 + j]) : -INFINITY;
    float mx = logit;
    #pragma unroll
    for (int s = 16; s; s >>= 1) mx = fmaxf(mx, __shfl_xor_sync(0xffffffffu, mx, s));
    float e = act ? __expf(logit - mx) : 0.f;
    float se = e;
    #pragma unroll
    for (int s = 16; s; s >>= 1) se += __shfl_xor_sync(0xffffffffu, se, s);
    const float aw = e / se;

    // ---- phase A: lanes 0..11 build the scalar package for point j ----
    const float rx = __ldg(&rp[bq * 2 + 0]);
    const float ry = __ldg(&rp[bq * 2 + 1]);

    int   I00 = 0, DXC = 0, DYC = 0;
    float w00 = 0.f, w01 = 0.f, w10 = 0.f, w11 = 0.f;
    {
        const int l  = j >> 2;
        const int Wl = 64 >> l;
        const int Hl = 64 >> l;
        const int st = (l == 0) ? 0 : ((l == 1) ? 4096 : 5120);

        float2 off = __ldg(reinterpret_cast<const float2*>(
            g_off + (size_t)bq * 192 + h * 24) + (act ? j : 0));

        float lx = fminf(fmaxf(rx + off.x, 0.f), 1.f);
        float ly = fminf(fmaxf(ry + off.y, 0.f), 1.f);
        float x = lx * (float)Wl - 0.5f;
        float y = ly * (float)Hl - 0.5f;
        float x0f = floorf(x), y0f = floorf(y);
        float wx = x - x0f,   wy = y - y0f;
        int x0 = (int)x0f, y0 = (int)y0f;

        int cx0 = max(x0, 0);
        int cy0 = max(y0, 0);
        int cx1 = min(x0 + 1, Wl - 1);
        int cy1 = min(y0 + 1, Hl - 1);
        float vx0 = (x0 >= 0)      ? 1.f : 0.f;
        float vx1 = (x0 + 1 < Wl)  ? 1.f : 0.f;
        float vy0 = (y0 >= 0)      ? 1.f : 0.f;
        float vy1 = (y0 + 1 < Hl)  ? 1.f : 0.f;

        float ax0 = (1.f - wx) * vx0, ax1 = wx * vx1;
        float ay0 = (1.f - wy) * vy0 * aw, ay1 = wy * vy1 * aw;
        w00 = ax0 * ay0; w01 = ax1 * ay0;
        w10 = ax0 * ay1; w11 = ax1 * ay1;

        I00 = (st + cy0 * Wl + cx0) * CDIM;
        DXC = (cx1 - cx0) * CDIM;
        DYC = (cy1 - cy0) * Wl * CDIM;
    }

    // ---- phase B: gather, lane = channel ----
    const float* vb = g_v + ((size_t)b * NVAL) * CDIM + h * HD + lane;
    float acc = 0.f;
    #pragma unroll
    for (int p = 0; p < LEVELS * POINTS; p++) {
        const int   I  = __shfl_sync(0xffffffffu, I00, p);
        const int   dx = __shfl_sync(0xffffffffu, DXC, p);
        const int   dy = __shfl_sync(0xffffffffu, DYC, p);
        const float a00 = __shfl_sync(0xffffffffu, w00, p);
        const float a01 = __shfl_sync(0xffffffffu, w01, p);
        const float a10 = __shfl_sync(0xffffffffu, w10, p);
        const float a11 = __shfl_sync(0xffffffffu, w11, p);
        const float* pt = vb + I;
        acc = fmaf(__ldg(pt),           a00, acc);
        acc = fmaf(__ldg(pt + dx),      a01, acc);
        acc = fmaf(__ldg(pt + dy),      a10, acc);
        acc = fmaf(__ldg(pt + dx + dy), a11, acc);
    }
    g_attn[(size_t)bq * CDIM + h * HD + lane] = acc;
}

// ---------------------------------------------------------------------------
extern "C" void kernel_launch(void* const* d_in, const int* in_sizes, int n_in,
                              void* d_out, int out_size)
{
    const float* query = (const float*)d_in[0];
    const float* refp  = (const float*)d_in[1];
    const float* value = (const float*)d_in[2];
    const float* Wv    = (const float*)d_in[3];
    const float* bv    = (const float*)d_in[4];
    const float* Woff  = (const float*)d_in[5];
    const float* boff  = (const float*)d_in[6];
    const float* Wa    = (const float*)d_in[7];
    const float* ba    = (const float*)d_in[8];
    const float* Wo    = (const float*)d_in[9];
    const float* bo    = (const float*)d_in[10];
    float* out = (float*)d_out;

    float* pv;   cudaGetSymbolAddress((void**)&pv,   g_v);
    float* poff; cudaGetSymbolAddress((void**)&poff, g_off);
    float* pa;   cudaGetSymbolAddress((void**)&pa,   g_a);
    float* patt; cudaGetSymbolAddress((void**)&patt, g_attn);

    const int mb = M_TOT / 128;   // 84

    // 1. v = value @ Wv^T + bv
    bf16_gemm<<<dim3(2, mb), 256>>>(value, Wv, bv, pv, 256);
    // 2. off = query @ Woff^T + boff
    bf16_gemm<<<dim3(2, mb), 256>>>(query, Woff, boff, poff, 192);
    // 3. a = query @ Wa^T + ba
    bf16_gemm<<<dim3(1, mb), 256>>>(query, Wa, ba, pa, 96);
    // 4. sampling (one warp per (b,q,h))
    {
        int warps  = BB * NQ * HEADS;              // 86016
        int blocks = (warps + 7) / 8;
        msda_sample<<<blocks, 256>>>(refp);
    }
    // 5. out = attn @ Wo^T + bo
    bf16_gemm<<<dim3(2, mb), 256>>>(patt, Wo, bo, out, 256);
}